// round 4
// baseline (speedup 1.0000x reference)
#include <cuda_runtime.h>
#include <cuda_bf16.h>
#include <cstdint>

#define NN 110
#define CC 4096
#define NPAD 128

#define BM 128
#define BN 32
#define BKC 64          // k per chunk (bf16 elems)
#define PITCH 72        // bf16 elems per smem row (64 + 8 pad)
#define NTH 256

// -------------------- scratch (zero-initialized device globals) ------------
// hi/lo bf16 split buffers. Rows >= 110 are never written -> stay zero.
__device__ __nv_bfloat16 g_xh[NPAD * CC], g_xl[NPAD * CC];
__device__ __nv_bfloat16 g_hh[NPAD * CC], g_hl[NPAD * CC];
__device__ __nv_bfloat16 g_ah[NPAD * CC], g_al[NPAD * CC];
__device__ __nv_bfloat16 g_oh[NPAD * CC], g_ol[NPAD * CC];
__device__ __nv_bfloat16 g_Mnh[NPAD * NPAD], g_Mnl[NPAD * NPAD];
__device__ __nv_bfloat16 g_Wlh[NPAD * NPAD], g_Wll[NPAD * NPAD];

// -------------------- helpers ----------------------------------------------
__device__ __forceinline__ uint32_t smem_u32(const void* p) {
    uint32_t a;
    asm("{ .reg .u64 t; cvta.to.shared.u64 t, %1; cvt.u32.u64 %0, t; }"
        : "=r"(a) : "l"(p));
    return a;
}

// split fp32 pair -> packed bf16x2 hi word and lo word (lo = rn(x - hi))
__device__ __forceinline__ void split2(float x0, float x1, uint32_t& hi, uint32_t& lo) {
    uint32_t h;
    asm("cvt.rn.bf16x2.f32 %0, %1, %2;" : "=r"(h) : "f"(x1), "f"(x0));
    float h0 = __uint_as_float(h << 16);
    float h1 = __uint_as_float(h & 0xFFFF0000u);
    float r0 = x0 - h0;
    float r1 = x1 - h1;
    asm("cvt.rn.bf16x2.f32 %0, %1, %2;" : "=r"(lo) : "f"(r1), "f"(r0));
    hi = h;
}

#define LDMX4(r, addr)                                                        \
    asm volatile("ldmatrix.sync.aligned.m8n8.x4.shared.b16 {%0,%1,%2,%3}, [%4];" \
        : "=r"((r)[0]), "=r"((r)[1]), "=r"((r)[2]), "=r"((r)[3]) : "r"(addr))

#define MMA_BF16(acc, a, b0, b1)                                              \
    asm volatile("mma.sync.aligned.m16n8k16.row.col.f32.bf16.bf16.f32 "       \
        "{%0,%1,%2,%3}, {%4,%5,%6,%7}, {%8,%9}, {%0,%1,%2,%3};"               \
        : "+f"((acc)[0]), "+f"((acc)[1]), "+f"((acc)[2]), "+f"((acc)[3])      \
        : "r"((a)[0]), "r"((a)[1]), "r"((a)[2]), "r"((a)[3]), "r"(b0), "r"(b1))

// ---------------------------------------------------------------------------
// Prep A: split x into hi/lo bf16 (linear over 110*4096 elems, 8 per thread)
// ---------------------------------------------------------------------------
__global__ void split_x_kernel(const float* __restrict__ src) {
    int e = (blockIdx.x * blockDim.x + threadIdx.x) * 8;
    if (e >= NN * CC) return;
    float4 a = *(const float4*)(src + e);
    float4 b = *(const float4*)(src + e + 4);
    uint4 hv, lv;
    split2(a.x, a.y, hv.x, lv.x);
    split2(a.z, a.w, hv.y, lv.y);
    split2(b.x, b.y, hv.z, lv.z);
    split2(b.z, b.w, hv.w, lv.w);
    *(uint4*)&g_xh[e] = hv;
    *(uint4*)&g_xl[e] = lv;
}

// ---------------------------------------------------------------------------
// Prep B: Mn[j][i] = (adj[i][j]!=0)/max(deg_j,1), Wl padded; both as hi/lo bf16
// ---------------------------------------------------------------------------
__global__ void prep_kernel(const int* __restrict__ adj, const float* __restrict__ Wl) {
    int j = threadIdx.x;
    if (j >= NPAD) return;
    float inv = 0.0f;
    if (j < NN) {
        int deg = 0;
        for (int i = 0; i < NN; ++i) deg += (adj[i * NN + j] != 0);
        inv = 1.0f / (float)(deg > 1 ? deg : 1);
    }
    for (int i = 0; i < NPAD; ++i) {
        float mv = 0.0f, wv = 0.0f;
        if (j < NN && i < NN) {
            if (adj[i * NN + j] != 0) mv = inv;
            wv = Wl[j * NN + i];
        }
        __nv_bfloat16 mh = __float2bfloat16(mv);
        __nv_bfloat16 wh = __float2bfloat16(wv);
        g_Mnh[j * NPAD + i] = mh;
        g_Mnl[j * NPAD + i] = __float2bfloat16(mv - __bfloat162float(mh));
        g_Wlh[j * NPAD + i] = wh;
        g_Wll[j * NPAD + i] = __float2bfloat16(wv - __bfloat162float(wh));
    }
}

// ---------------------------------------------------------------------------
// bf16-split HMMA GEMM. A always pre-split bf16 hi/lo (128 padded rows).
// B: fp32 (BSPLIT=0, converted in-kernel) or pre-split bf16 (BSPLIT=1).
// Output: hi/lo bf16 pair (OSPLIT=1) or fp32 (OSPLIT=0).
// Optional second (A2,B2f) pair for the concat GEMM (only with BSPLIT=0).
// ---------------------------------------------------------------------------
template<int BSPLIT, int OSPLIT>
__global__ __launch_bounds__(NTH)
void tgemm(const __nv_bfloat16* __restrict__ Ah1, const __nv_bfloat16* __restrict__ Al1,
           int lda1, int ka1,
           const float* __restrict__ B1f,
           const __nv_bfloat16* __restrict__ B1h, const __nv_bfloat16* __restrict__ B1l,
           int ldb1,
           const __nv_bfloat16* __restrict__ Ah2, const __nv_bfloat16* __restrict__ Al2,
           int lda2, int ka2,
           const float* __restrict__ B2f, int ldb2,
           const float* __restrict__ bias, int bias_mode, int do_relu,
           float* __restrict__ C,
           __nv_bfloat16* __restrict__ Ch, __nv_bfloat16* __restrict__ Cl,
           int ldc, int Mreal)
{
    __shared__ __align__(16) __nv_bfloat16 AsH[BM * PITCH];
    __shared__ __align__(16) __nv_bfloat16 AsL[BM * PITCH];
    __shared__ __align__(16) __nv_bfloat16 BsH[BN * PITCH];
    __shared__ __align__(16) __nv_bfloat16 BsL[BN * PITCH];

    const int tid = threadIdx.x;
    const int wid = tid >> 5;
    const int lid = tid & 31;
    const int warpm = wid >> 1;
    const int warpn = wid & 1;
    const int n0 = blockIdx.x * BN;

    // A loader: 128 rows x 64 k bf16; 2 threads/row, 32 elems each (4x uint4)
    const int ar = tid >> 1;
    const int ac = (tid & 1) * 32;
    // B loader: 64 k x 32 n; thread covers 8 consecutive k for one n
    const int bkb = (tid >> 5) * 8;
    const int bnn = tid & 31;

    const int T1 = ka1 / BKC;
    const int T2 = (Ah2 != nullptr) ? (ka2 / BKC) : 0;
    const int T  = T1 + T2;

    float acc[2][2][4];
#pragma unroll
    for (int a = 0; a < 2; ++a)
#pragma unroll
        for (int b = 0; b < 2; ++b)
#pragma unroll
            for (int c = 0; c < 4; ++c) acc[a][b][c] = 0.0f;

    // ldmatrix bases (same fragment layout as the R3 kernel, which validated)
    const uint32_t aRowSel = (uint32_t)(lid & 15);
    const uint32_t aColSel = (uint32_t)((lid >> 4) & 1) * 8u;
    uint32_t aBaseH = smem_u32(AsH) + ((warpm * 32 + aRowSel) * PITCH + aColSel) * 2u;
    uint32_t aBaseL = smem_u32(AsL) + ((warpm * 32 + aRowSel) * PITCH + aColSel) * 2u;
    const uint32_t bRowSel = (uint32_t)((lid & 7) + ((lid >> 4) & 1) * 8);
    const uint32_t bColSel = (uint32_t)(lid & 8);
    uint32_t bBaseH = smem_u32(BsH) + ((warpn * 16 + bRowSel) * PITCH + bColSel) * 2u;
    uint32_t bBaseL = smem_u32(BsL) + ((warpn * 16 + bRowSel) * PITCH + bColSel) * 2u;

    uint4 rah[4], ral[4];
    float fb[8];
    unsigned short bh16[8], bl16[8];

#define LOADG(T_)                                                              \
    do {                                                                       \
        const __nv_bfloat16* Ah; const __nv_bfloat16* Al;                      \
        const float* Bf; int lda_, ldb_, k0_;                                  \
        if ((T_) < T1) { Ah = Ah1; Al = Al1; Bf = B1f; lda_ = lda1; ldb_ = ldb1; k0_ = (T_) * BKC; } \
        else { Ah = Ah2; Al = Al2; Bf = B2f; lda_ = lda2; ldb_ = ldb2; k0_ = ((T_) - T1) * BKC; }    \
        _Pragma("unroll")                                                      \
        for (int j = 0; j < 4; ++j) {                                          \
            size_t off = (size_t)ar * lda_ + k0_ + ac + j * 8;                 \
            rah[j] = *(const uint4*)(Ah + off);                                \
            ral[j] = *(const uint4*)(Al + off);                                \
        }                                                                      \
        if (BSPLIT) {                                                          \
            _Pragma("unroll")                                                  \
            for (int i = 0; i < 8; ++i) {                                      \
                size_t off = (size_t)(k0_ + bkb + i) * ldb_ + n0 + bnn;        \
                bh16[i] = *(const unsigned short*)(B1h + off);                 \
                bl16[i] = *(const unsigned short*)(B1l + off);                 \
            }                                                                  \
        } else {                                                               \
            _Pragma("unroll")                                                  \
            for (int i = 0; i < 8; ++i)                                        \
                fb[i] = Bf[(size_t)(k0_ + bkb + i) * ldb_ + n0 + bnn];         \
        }                                                                      \
    } while (0)

    LOADG(0);

    for (int t = 0; t < T; ++t) {
        __syncthreads();

        // ---- stage to smem ----
#pragma unroll
        for (int j = 0; j < 4; ++j) {
            uint32_t off = (uint32_t)ar * PITCH + (uint32_t)(ac + j * 8);
            *(uint4*)&AsH[off] = rah[j];
            *(uint4*)&AsL[off] = ral[j];
        }
        {
            uint4 hv, lv;
            if (BSPLIT) {
                hv.x = (uint32_t)bh16[0] | ((uint32_t)bh16[1] << 16);
                hv.y = (uint32_t)bh16[2] | ((uint32_t)bh16[3] << 16);
                hv.z = (uint32_t)bh16[4] | ((uint32_t)bh16[5] << 16);
                hv.w = (uint32_t)bh16[6] | ((uint32_t)bh16[7] << 16);
                lv.x = (uint32_t)bl16[0] | ((uint32_t)bl16[1] << 16);
                lv.y = (uint32_t)bl16[2] | ((uint32_t)bl16[3] << 16);
                lv.z = (uint32_t)bl16[4] | ((uint32_t)bl16[5] << 16);
                lv.w = (uint32_t)bl16[6] | ((uint32_t)bl16[7] << 16);
            } else {
                split2(fb[0], fb[1], hv.x, lv.x);
                split2(fb[2], fb[3], hv.y, lv.y);
                split2(fb[4], fb[5], hv.z, lv.z);
                split2(fb[6], fb[7], hv.w, lv.w);
            }
            uint32_t off = (uint32_t)bnn * PITCH + (uint32_t)bkb;
            *(uint4*)&BsH[off] = hv;
            *(uint4*)&BsL[off] = lv;
        }
        __syncthreads();

        if (t + 1 < T) LOADG(t + 1);

        // ---- compute: 4 k-steps of 16 ----
#pragma unroll
        for (int ks = 0; ks < 4; ++ks) {
            uint32_t ah[2][4], al[2][4], bh[4], bl[4];
            const uint32_t ko = (uint32_t)ks * 32u;
            LDMX4(ah[0], aBaseH + ko);
            LDMX4(ah[1], aBaseH + 16u * PITCH * 2u + ko);
            LDMX4(al[0], aBaseL + ko);
            LDMX4(al[1], aBaseL + 16u * PITCH * 2u + ko);
            LDMX4(bh, bBaseH + ko);
            LDMX4(bl, bBaseL + ko);
#pragma unroll
            for (int mt = 0; mt < 2; ++mt)
#pragma unroll
                for (int nt = 0; nt < 2; ++nt) {
                    MMA_BF16(acc[mt][nt], ah[mt], bh[2 * nt], bh[2 * nt + 1]);
                    MMA_BF16(acc[mt][nt], ah[mt], bl[2 * nt], bl[2 * nt + 1]);
                    MMA_BF16(acc[mt][nt], al[mt], bh[2 * nt], bh[2 * nt + 1]);
                }
        }
    }
#undef LOADG

    // ---- epilogue ----
    const int g  = lid >> 2;
    const int tq = lid & 3;
#pragma unroll
    for (int mt = 0; mt < 2; ++mt) {
#pragma unroll
        for (int nt = 0; nt < 2; ++nt) {
            int col = n0 + warpn * 16 + nt * 8 + tq * 2;
            float bc0 = 0.f, bc1 = 0.f;
            if (bias_mode == 1) { bc0 = bias[col]; bc1 = bias[col + 1]; }
            int m0 = warpm * 32 + mt * 16 + g;
            int m1 = m0 + 8;
#pragma unroll
            for (int half = 0; half < 2; ++half) {
                int m = half ? m1 : m0;
                if (m >= Mreal) continue;
                float rb = (bias_mode == 2) ? bias[m] : 0.0f;
                float vx = acc[mt][nt][half * 2 + 0] + bc0 + rb;
                float vy = acc[mt][nt][half * 2 + 1] + bc1 + rb;
                if (do_relu) { vx = fmaxf(vx, 0.f); vy = fmaxf(vy, 0.f); }
                if (OSPLIT) {
                    uint32_t hw, lw;
                    split2(vx, vy, hw, lw);
                    size_t off = (size_t)m * ldc + col;
                    *(uint32_t*)(Ch + off) = hw;
                    *(uint32_t*)(Cl + off) = lw;
                } else {
                    *(float2*)&C[(size_t)m * ldc + col] = make_float2(vx, vy);
                }
            }
        }
    }
}

// ---------------------------------------------------------------------------
extern "C" void kernel_launch(void* const* d_in, const int* in_sizes, int n_in,
                              void* d_out, int out_size)
{
    const float* x   = (const float*)d_in[0];
    const int*   adj = (const int*)  d_in[1];
    const float* W2  = (const float*)d_in[2];
    const float* b2  = (const float*)d_in[3];
    const float* W1  = (const float*)d_in[4];
    const float* b1  = (const float*)d_in[5];
    const float* Wl  = (const float*)d_in[6];
    const float* bl  = (const float*)d_in[7];
    float* out = (float*)d_out;

    __nv_bfloat16 *xh, *xl, *hh, *hl, *ah, *al, *oh, *ol, *Mnh, *Mnl, *Wlh, *Wll;
    cudaGetSymbolAddress((void**)&xh, g_xh);   cudaGetSymbolAddress((void**)&xl, g_xl);
    cudaGetSymbolAddress((void**)&hh, g_hh);   cudaGetSymbolAddress((void**)&hl, g_hl);
    cudaGetSymbolAddress((void**)&ah, g_ah);   cudaGetSymbolAddress((void**)&al, g_al);
    cudaGetSymbolAddress((void**)&oh, g_oh);   cudaGetSymbolAddress((void**)&ol, g_ol);
    cudaGetSymbolAddress((void**)&Mnh, g_Mnh); cudaGetSymbolAddress((void**)&Mnl, g_Mnl);
    cudaGetSymbolAddress((void**)&Wlh, g_Wlh); cudaGetSymbolAddress((void**)&Wll, g_Wll);

    dim3 g(CC / BN), b(NTH);   // 128 CTAs

    split_x_kernel<<<(NN * CC / 8 + 255) / 256, 256>>>(x);
    prep_kernel<<<1, NPAD>>>(adj, Wl);

    // K1: h = x @ W2 + b2   (B fp32, out split)
    tgemm<0, 1><<<g, b>>>(xh, xl, CC, CC,
                          W2, nullptr, nullptr, CC,
                          nullptr, nullptr, 0, 0, nullptr, 0,
                          b2, 1, 0,
                          nullptr, hh, hl, CC, NN);
    // K2: aggr = Mn @ h     (B pre-split, out split)
    tgemm<1, 1><<<g, b>>>(Mnh, Mnl, NPAD, NPAD,
                          nullptr, hh, hl, CC,
                          nullptr, nullptr, 0, 0, nullptr, 0,
                          nullptr, 0, 0,
                          nullptr, ah, al, CC, NN);
    // K3: out1 = relu(h @ W1_top + aggr @ W1_bot + b1)  (B fp32 dual, out split)
    tgemm<0, 1><<<g, b>>>(hh, hl, CC, CC,
                          W1, nullptr, nullptr, CC,
                          ah, al, CC, CC, W1 + (size_t)CC * CC, CC,
                          b1, 1, 1,
                          nullptr, oh, ol, CC, NN);
    // K4: out = Wlp @ out1 + bl[:,None]   (B pre-split, out fp32)
    tgemm<1, 0><<<g, b>>>(Wlh, Wll, NPAD, NPAD,
                          nullptr, oh, ol, CC,
                          nullptr, nullptr, 0, 0, nullptr, 0,
                          bl, 2, 0,
                          out, nullptr, nullptr, CC, NN);
}

// round 5
// speedup vs baseline: 1.6903x; 1.6903x over previous
#include <cuda_runtime.h>
#include <cuda_bf16.h>
#include <cstdint>

#define NN 110
#define CC 4096
#define NPAD 128

#define BM 128
#define BN 32
#define BKC 64          // fp32 k per chunk
#define PITCH 72        // bf16 elems per smem row (64 + 8 pad)
#define NTH 256

// double-buffered stage layout (bytes within dynamic smem)
#define AH_OFF 0
#define AL_OFF 18432
#define BH_OFF 36864
#define BL_OFF 41472
#define STAGE  46080
#define DSMEM  (2 * STAGE)

// -------------------- scratch (zero-initialized device globals) ------------
__device__ float g_h   [NPAD * CC];
__device__ float g_aggr[NPAD * CC];
__device__ float g_out1[NPAD * CC];
__device__ float g_Mn  [NPAD * NPAD];
__device__ float g_Wlp [NPAD * NPAD];

// -------------------- helpers ----------------------------------------------
__device__ __forceinline__ uint32_t smem_u32(const void* p) {
    uint32_t a;
    asm("{ .reg .u64 t; cvta.to.shared.u64 t, %1; cvt.u32.u64 %0, t; }"
        : "=r"(a) : "l"(p));
    return a;
}

// split fp32 pair -> packed bf16x2 hi word and lo word (lo = rn(x - hi))
__device__ __forceinline__ void split2(float x0, float x1, uint32_t& hi, uint32_t& lo) {
    uint32_t h;
    asm("cvt.rn.bf16x2.f32 %0, %1, %2;" : "=r"(h) : "f"(x1), "f"(x0));
    float h0 = __uint_as_float(h << 16);
    float h1 = __uint_as_float(h & 0xFFFF0000u);
    float r0 = x0 - h0;
    float r1 = x1 - h1;
    asm("cvt.rn.bf16x2.f32 %0, %1, %2;" : "=r"(lo) : "f"(r1), "f"(r0));
    hi = h;
}

#define LDMX4(r, addr)                                                        \
    asm volatile("ldmatrix.sync.aligned.m8n8.x4.shared.b16 {%0,%1,%2,%3}, [%4];" \
        : "=r"((r)[0]), "=r"((r)[1]), "=r"((r)[2]), "=r"((r)[3]) : "r"(addr))

#define MMA_BF16(acc, a, b0, b1)                                              \
    asm volatile("mma.sync.aligned.m16n8k16.row.col.f32.bf16.bf16.f32 "       \
        "{%0,%1,%2,%3}, {%4,%5,%6,%7}, {%8,%9}, {%0,%1,%2,%3};"               \
        : "+f"((acc)[0]), "+f"((acc)[1]), "+f"((acc)[2]), "+f"((acc)[3])      \
        : "r"((a)[0]), "r"((a)[1]), "r"((a)[2]), "r"((a)[3]), "r"(b0), "r"(b1))

// ---------------------------------------------------------------------------
// Prep (parallel): Mn[j][i] = (adj[i][j]!=0)/max(deg_j,1); Wl padded to 128.
// grid=128 (j), block=128 (i)
// ---------------------------------------------------------------------------
__global__ void prep_kernel(const int* __restrict__ adj, const float* __restrict__ Wl) {
    const int j = blockIdx.x;
    const int i = threadIdx.x;
    __shared__ int sdeg[NPAD];
    int a = (i < NN && j < NN) ? (adj[i * NN + j] != 0) : 0;
    sdeg[i] = a;
    __syncthreads();
#pragma unroll
    for (int s = 64; s > 0; s >>= 1) {
        if (i < s) sdeg[i] += sdeg[i + s];
        __syncthreads();
    }
    const int deg = sdeg[0];
    const float inv = (j < NN) ? 1.0f / (float)(deg > 1 ? deg : 1) : 0.0f;
    g_Mn [j * NPAD + i] = a ? inv : 0.0f;
    g_Wlp[j * NPAD + i] = (i < NN && j < NN) ? Wl[j * NN + i] : 0.0f;
}

// ---------------------------------------------------------------------------
// bf16-split HMMA GEMM (mma.sync m16n8k16), double-buffered smem pipeline:
//   C[0:Mreal, n0:n0+32] = A1[Mreal x ka1] @ B1[ka1 x N] (+ A2 @ B2) (+ bias)
// ---------------------------------------------------------------------------
__global__ __launch_bounds__(NTH)
void tgemm(const float* __restrict__ A1, int lda1, int ka1,
           const float* __restrict__ B1, int ldb1,
           const float* __restrict__ A2, int lda2, int ka2,
           const float* __restrict__ B2, int ldb2,
           const float* __restrict__ bias, int bias_mode, int do_relu,
           float* __restrict__ C, int ldc, int Mreal)
{
    extern __shared__ __align__(16) char dsm[];
    const uint32_t sb = smem_u32(dsm);

    const int tid = threadIdx.x;
    const int wid = tid >> 5;
    const int lid = tid & 31;
    const int warpm = wid >> 1;      // 0..3  -> m base warpm*32
    const int warpn = wid & 1;       // 0..1  -> n base warpn*16
    const int n0 = blockIdx.x * BN;

    // A loader: 128 rows x 64 k fp32, float4, 8 passes (16 threads/row)
    const int alrow = tid >> 4;          // 0..15
    const int alc   = (tid & 15) * 4;    // k offset in floats
    // B loader: 64 k x 32 n, coalesced along n
    const int bkb = (tid >> 5) * 8;      // 8 k per thread
    const int bnn = tid & 31;            // n index

    const int T1 = ka1 / BKC;
    const int T2 = (A2 != nullptr) ? (ka2 / BKC) : 0;
    const int T  = T1 + T2;

    float acc[2][2][4];
#pragma unroll
    for (int a = 0; a < 2; ++a)
#pragma unroll
        for (int b = 0; b < 2; ++b)
#pragma unroll
            for (int c = 0; c < 4; ++c) acc[a][b][c] = 0.0f;

    // ldmatrix lane byte-offsets within a stage
    const uint32_t aRowSel = (uint32_t)(lid & 15);
    const uint32_t aColSel = (uint32_t)((lid >> 4) & 1) * 8u;
    const uint32_t aoffH = AH_OFF + ((warpm * 32 + aRowSel) * PITCH + aColSel) * 2u;
    const uint32_t aoffL = AL_OFF + ((warpm * 32 + aRowSel) * PITCH + aColSel) * 2u;
    const uint32_t bRowSel = (uint32_t)((lid & 7) + ((lid >> 4) & 1) * 8);
    const uint32_t bColSel = (uint32_t)(lid & 8);
    const uint32_t boffH = BH_OFF + ((warpn * 16 + bRowSel) * PITCH + bColSel) * 2u;
    const uint32_t boffL = BL_OFF + ((warpn * 16 + bRowSel) * PITCH + bColSel) * 2u;

    float4 fa[8];
    float  fb[8];
    const float4 f4z = make_float4(0.f, 0.f, 0.f, 0.f);

#define LOADG(T_)                                                              \
    do {                                                                       \
        const float* A; const float* B; int lda_, ldb_, k0_;                   \
        if ((T_) < T1) { A = A1; B = B1; lda_ = lda1; ldb_ = ldb1; k0_ = (T_) * BKC; } \
        else { A = A2; B = B2; lda_ = lda2; ldb_ = ldb2; k0_ = ((T_) - T1) * BKC; }    \
        _Pragma("unroll")                                                      \
        for (int p = 0; p < 8; ++p) {                                          \
            int m = p * 16 + alrow;                                            \
            fa[p] = (m < Mreal) ? *(const float4*)(A + (size_t)m * lda_ + k0_ + alc) : f4z; \
        }                                                                      \
        _Pragma("unroll")                                                      \
        for (int i = 0; i < 8; ++i)                                            \
            fb[i] = B[(size_t)(k0_ + bkb + i) * ldb_ + n0 + bnn];              \
    } while (0)

    // convert + store regs -> stage buffer 'bufsel'
#define STORE_STAGE(bufsel)                                                    \
    do {                                                                       \
        char* st = dsm + (bufsel) * STAGE;                                     \
        _Pragma("unroll")                                                      \
        for (int p = 0; p < 8; ++p) {                                          \
            int row = p * 16 + alrow;                                          \
            uint32_t h0, l0, h1, l1;                                           \
            split2(fa[p].x, fa[p].y, h0, l0);                                  \
            split2(fa[p].z, fa[p].w, h1, l1);                                  \
            uint32_t off = ((uint32_t)row * PITCH + (uint32_t)alc) * 2u;       \
            *(uint2*)(st + AH_OFF + off) = make_uint2(h0, h1);                 \
            *(uint2*)(st + AL_OFF + off) = make_uint2(l0, l1);                 \
        }                                                                      \
        {                                                                      \
            uint4 hv, lv;                                                      \
            split2(fb[0], fb[1], hv.x, lv.x);                                  \
            split2(fb[2], fb[3], hv.y, lv.y);                                  \
            split2(fb[4], fb[5], hv.z, lv.z);                                  \
            split2(fb[6], fb[7], hv.w, lv.w);                                  \
            uint32_t off = ((uint32_t)bnn * PITCH + (uint32_t)bkb) * 2u;       \
            *(uint4*)(st + BH_OFF + off) = hv;                                 \
            *(uint4*)(st + BL_OFF + off) = lv;                                 \
        }                                                                      \
    } while (0)

    // prologue: fill buffer 0, prefetch chunk 1 into regs
    LOADG(0);
    STORE_STAGE(0);
    if (T > 1) LOADG(1);
    __syncthreads();

    for (int t = 0; t < T; ++t) {
        const int p = t & 1;
        const uint32_t base = sb + (uint32_t)p * STAGE;

        // ---- MMA on buffer p (4 k-steps of 16) ----
#pragma unroll
        for (int ks = 0; ks < 4; ++ks) {
            uint32_t ah[2][4], al[2][4], bh[4], bl[4];
            const uint32_t ko = (uint32_t)ks * 32u;
            LDMX4(ah[0], base + aoffH + ko);
            LDMX4(ah[1], base + aoffH + 16u * PITCH * 2u + ko);
            LDMX4(al[0], base + aoffL + ko);
            LDMX4(al[1], base + aoffL + 16u * PITCH * 2u + ko);
            LDMX4(bh, base + boffH + ko);
            LDMX4(bl, base + boffL + ko);
#pragma unroll
            for (int mt = 0; mt < 2; ++mt)
#pragma unroll
                for (int nt = 0; nt < 2; ++nt) {
                    MMA_BF16(acc[mt][nt], ah[mt], bh[2 * nt], bh[2 * nt + 1]);
                    MMA_BF16(acc[mt][nt], ah[mt], bl[2 * nt], bl[2 * nt + 1]);
                    MMA_BF16(acc[mt][nt], al[mt], bh[2 * nt], bh[2 * nt + 1]);
                }
        }

        // ---- stage chunk t+1 into the other buffer (overlaps tensor pipe) --
        if (t + 1 < T) STORE_STAGE(p ^ 1);
        // ---- prefetch chunk t+2 into regs ----
        if (t + 2 < T) LOADG(t + 2);

        __syncthreads();
    }
#undef LOADG
#undef STORE_STAGE

    // ---- epilogue: fragment c: lane -> rows g, g+8; cols 2t, 2t+1 ----
    const int g  = lid >> 2;
    const int tq = lid & 3;
#pragma unroll
    for (int mt = 0; mt < 2; ++mt) {
#pragma unroll
        for (int nt = 0; nt < 2; ++nt) {
            int col = n0 + warpn * 16 + nt * 8 + tq * 2;
            float bc0 = 0.f, bc1 = 0.f;
            if (bias_mode == 1) { bc0 = bias[col]; bc1 = bias[col + 1]; }
            int m0 = warpm * 32 + mt * 16 + g;
            int m1 = m0 + 8;
            if (m0 < Mreal) {
                float rb = (bias_mode == 2) ? bias[m0] : 0.0f;
                float2 v = make_float2(acc[mt][nt][0] + bc0 + rb,
                                       acc[mt][nt][1] + bc1 + rb);
                if (do_relu) { v.x = fmaxf(v.x, 0.f); v.y = fmaxf(v.y, 0.f); }
                *(float2*)&C[(size_t)m0 * ldc + col] = v;
            }
            if (m1 < Mreal) {
                float rb = (bias_mode == 2) ? bias[m1] : 0.0f;
                float2 v = make_float2(acc[mt][nt][2] + bc0 + rb,
                                       acc[mt][nt][3] + bc1 + rb);
                if (do_relu) { v.x = fmaxf(v.x, 0.f); v.y = fmaxf(v.y, 0.f); }
                *(float2*)&C[(size_t)m1 * ldc + col] = v;
            }
        }
    }
}

// ---------------------------------------------------------------------------
extern "C" void kernel_launch(void* const* d_in, const int* in_sizes, int n_in,
                              void* d_out, int out_size)
{
    const float* x   = (const float*)d_in[0];
    const int*   adj = (const int*)  d_in[1];
    const float* W2  = (const float*)d_in[2];
    const float* b2  = (const float*)d_in[3];
    const float* W1  = (const float*)d_in[4];
    const float* b1  = (const float*)d_in[5];
    const float* Wl  = (const float*)d_in[6];
    const float* bl  = (const float*)d_in[7];
    float* out = (float*)d_out;

    float *h, *aggr, *out1, *Mn, *Wlp;
    cudaGetSymbolAddress((void**)&h,    g_h);
    cudaGetSymbolAddress((void**)&aggr, g_aggr);
    cudaGetSymbolAddress((void**)&out1, g_out1);
    cudaGetSymbolAddress((void**)&Mn,   g_Mn);
    cudaGetSymbolAddress((void**)&Wlp,  g_Wlp);

    cudaFuncSetAttribute(tgemm, cudaFuncAttributeMaxDynamicSharedMemorySize, DSMEM);

    dim3 g(CC / BN), b(NTH);   // 128 CTAs

    prep_kernel<<<NPAD, NPAD>>>(adj, Wl);

    // K1: h = x @ W2 + b2
    tgemm<<<g, b, DSMEM>>>(x, CC, CC, W2, CC,
                           nullptr, 0, 0, nullptr, 0,
                           b2, 1, 0, h, CC, NN);
    // K2: aggr = Mn @ h
    tgemm<<<g, b, DSMEM>>>(Mn, NPAD, NPAD, h, CC,
                           nullptr, 0, 0, nullptr, 0,
                           nullptr, 0, 0, aggr, CC, NN);
    // K3: out1 = relu(h @ W1_top + aggr @ W1_bot + b1)
    tgemm<<<g, b, DSMEM>>>(h, CC, CC, W1, CC,
                           aggr, CC, CC, W1 + (size_t)CC * CC, CC,
                           b1, 1, 1, out1, CC, NN);
    // K4: out = Wlp @ out1 + bl[:, None]
    tgemm<<<g, b, DSMEM>>>(Wlp, NPAD, NPAD, out1, CC,
                           nullptr, 0, 0, nullptr, 0,
                           bl, 2, 0, out, CC, NN);
}